// round 9
// baseline (speedup 1.0000x reference)
#include <cuda_runtime.h>
#include <mma.h>
#include <cstdint>
#include <cstddef>

using namespace nvcuda;

#define NN 10000
#define NE 320000
#define FD 256
#define EDF 64

// weight offsets inside g_wr
#define OW1 0
#define OM1 (FD * FD)
#define OM2 (OM1 + 576 * FD)
#define OW2 (OM2 + 576 * FD)
#define WTOT (OW2 + FD * FD)

// ---------------- scratch ----------------
__device__ float g_h0[NN * FD];
__device__ float g_h1[NN * FD];
__device__ float g_Xs[NN * FD];
__device__ float g_Xd[NN * FD];
__device__ float g_xr[NN * FD];
__device__ float g_efr[(size_t)NE * EDF];
__device__ float g_wr[WTOT];

__device__ __forceinline__ float gelu_f(float v) {
    float u = 0.7978845608028654f * (v + 0.044715f * v * v * v);
    float t;
    asm("tanh.approx.f32 %0, %1;" : "=f"(t) : "f"(u));
    return 0.5f * v * (1.0f + t);
}

__device__ __forceinline__ void cp16(uint32_t dst, const void* src, bool p) {
    asm volatile("cp.async.ca.shared.global [%0], [%1], 16, %2;"
                 :: "r"(dst), "l"(src), "r"(p ? 16 : 0));
}
#define CP_COMMIT() asm volatile("cp.async.commit_group;")
#define CP_WAIT(n)  asm volatile("cp.async.wait_group %0;" :: "n"(n))

// vectorized fire-and-forget reduction (PTX ISA 8.1, sm_90+)
__device__ __forceinline__ void red_add_v4(float* ptr, float4 v) {
    asm volatile("red.global.add.v4.f32 [%0], {%1, %2, %3, %4};"
                 :: "l"(ptr), "f"(v.x), "f"(v.y), "f"(v.z), "f"(v.w) : "memory");
}

// ---------------- tf32 pre-round: x, ef, all weights in ONE launch ----------------
__global__ void round_all(const float* __restrict__ x, const float* __restrict__ ef,
                          const float* __restrict__ wff1, const float* __restrict__ wmp1,
                          const float* __restrict__ wmp2, const float* __restrict__ wff2,
                          float* __restrict__ xr, float* __restrict__ efr,
                          float* __restrict__ wr) {
    const int NX4 = NN * FD / 4;
    const int NE4 = NE * EDF / 4;
    const int W14 = FD * FD / 4, WM4 = 576 * FD / 4;
    long long i = (long long)blockIdx.x * blockDim.x + threadIdx.x;
    const float4* s;
    float4* d;
    long long j = i;
    if (j < NX4) { s = (const float4*)x; d = (float4*)xr; }
    else {
        j -= NX4;
        if (j < NE4) { s = (const float4*)ef; d = (float4*)efr; }
        else {
            j -= NE4;
            if (j < W14) { s = (const float4*)wff1; d = (float4*)(wr + OW1); }
            else {
                j -= W14;
                if (j < WM4) { s = (const float4*)wmp1; d = (float4*)(wr + OM1); }
                else {
                    j -= WM4;
                    if (j < WM4) { s = (const float4*)wmp2; d = (float4*)(wr + OM2); }
                    else {
                        j -= WM4;
                        if (j >= W14) return;
                        s = (const float4*)wff2; d = (float4*)(wr + OW2);
                    }
                }
            }
        }
    }
    float4 v = s[j];
    v.x = wmma::__float_to_tf32(v.x);
    v.y = wmma::__float_to_tf32(v.y);
    v.z = wmma::__float_to_tf32(v.z);
    v.w = wmma::__float_to_tf32(v.w);
    d[j] = v;
}

__global__ void copy_kernel(const float4* __restrict__ a, float4* __restrict__ b, int n4) {
    int i = blockIdx.x * blockDim.x + threadIdx.x;
    if (i < n4) b[i] = a[i];
}

// ---------------- node GEMM: cp.async 2-stage, cvt-free when inputs pre-rounded ----------------
template <int CVT_A>
__global__ void __launch_bounds__(256) gemm_node(
    const float* __restrict__ A,
    const float* __restrict__ B0, const float* __restrict__ B1,
    const float* __restrict__ bias,
    const float* __restrict__ resid,
    float* __restrict__ C0, float* __restrict__ C1,
    float* __restrict__ Cdup,
    int M, int dogelu, int roundout)
{
    constexpr int BM = 128, BN = 64, BK = 32;
    constexpr int LDA = 36, LDB = 68;
    constexpr int STG = BM * LDA + BK * LDB;
    __shared__ __align__(16) float sm[2 * STG];
    float* Cs = sm;

    int tid = threadIdx.x;
    int warp = tid >> 5;
    int wm = warp >> 1, wn = warp & 1;
    int bm = blockIdx.x * BM;
    int sel = blockIdx.y >> 2;
    int cg = blockIdx.y & 3;
    const float* B = sel ? B1 : B0;
    float* C = sel ? C1 : C0;
    int bn = cg * BN;

    int lra = tid >> 3, lca = (tid & 7) << 2;
    int lrb = tid >> 4, lcb = (tid & 15) << 2;

    auto issue = [&](int st, int k0) {
        float* As = sm + st * STG;
        float* Bs = As + BM * LDA;
#pragma unroll
        for (int p = 0; p < 4; p++) {
            int row = lra + 32 * p;
            int grow = bm + row;
            cp16((uint32_t)__cvta_generic_to_shared(As + row * LDA + lca),
                 A + (size_t)grow * FD + k0 + lca, grow < M);
        }
#pragma unroll
        for (int p = 0; p < 2; p++) {
            int row = lrb + 16 * p;
            cp16((uint32_t)__cvta_generic_to_shared(Bs + row * LDB + lcb),
                 B + (size_t)(k0 + row) * FD + bn + lcb, true);
        }
    };

    wmma::fragment<wmma::accumulator, 16, 16, 8, float> acc[2][2];
#pragma unroll
    for (int i = 0; i < 2; i++)
#pragma unroll
        for (int j = 0; j < 2; j++) wmma::fill_fragment(acc[i][j], 0.0f);

    issue(0, 0);
    CP_COMMIT();

    constexpr int NIT = FD / BK;  // 8
#pragma unroll 1
    for (int it = 0; it < NIT; it++) {
        if (it + 1 < NIT) {
            issue((it + 1) & 1, (it + 1) * BK);
            CP_COMMIT();
            CP_WAIT(1);
        } else {
            CP_WAIT(0);
        }
        __syncthreads();
        float* As = sm + (it & 1) * STG;
        float* Bs = As + BM * LDA;
#pragma unroll
        for (int kk = 0; kk < BK; kk += 8) {
            wmma::fragment<wmma::matrix_a, 16, 16, 8, wmma::precision::tf32, wmma::row_major> a[2];
            wmma::fragment<wmma::matrix_b, 16, 16, 8, wmma::precision::tf32, wmma::row_major> b[2];
#pragma unroll
            for (int i = 0; i < 2; i++) {
                wmma::load_matrix_sync(a[i], As + (wm * 32 + i * 16) * LDA + kk, LDA);
                if (CVT_A) {
#pragma unroll
                    for (int e = 0; e < a[i].num_elements; e++)
                        a[i].x[e] = wmma::__float_to_tf32(a[i].x[e]);
                }
            }
#pragma unroll
            for (int j = 0; j < 2; j++)
                wmma::load_matrix_sync(b[j], Bs + kk * LDB + wn * 32 + j * 16, LDB);
#pragma unroll
            for (int i = 0; i < 2; i++)
#pragma unroll
                for (int j = 0; j < 2; j++)
                    wmma::mma_sync(acc[i][j], a[i], b[j], acc[i][j]);
        }
        __syncthreads();
    }

#pragma unroll
    for (int i = 0; i < 2; i++)
#pragma unroll
        for (int j = 0; j < 2; j++)
            wmma::store_matrix_sync(Cs + (wm * 32 + i * 16) * BN + wn * 32 + j * 16,
                                    acc[i][j], BN, wmma::mem_row_major);
    __syncthreads();
    for (int idx = tid; idx < BM * BN; idx += 256) {
        int r = idx >> 6, c = idx & 63;
        int grow = bm + r;
        if (grow >= M) continue;
        float v = Cs[idx];
        if (bias) v += bias[bn + c];
        if (dogelu) v = gelu_f(v);
        if (roundout) v = wmma::__float_to_tf32(v);
        if (resid) v += resid[(size_t)grow * FD + bn + c];
        C[(size_t)grow * FD + bn + c] = v;
        if (Cdup) Cdup[(size_t)grow * FD + bn + c] = v;
    }
}

// ---------------- direct-order fused edge kernel (v2: v4 reds, half-tile drain) ----------------
// Block: 128 consecutive edges x 2 column groups (grid.y selects which pair).
__global__ void __launch_bounds__(256) edge_direct(
    const float* __restrict__ ef,    // tf32-rounded
    const float* __restrict__ Wef,   // [64, 256] tf32-rounded
    const float* __restrict__ bias,
    const float* __restrict__ Xs, const float* __restrict__ Xd,
    const int* __restrict__ ei,      // src = ei[e], dst = ei[E+e]
    float* __restrict__ out,         // pre-seeded with hin
    int E)
{
    constexpr int CH = 128, LDA = 68, LDC = 68;
    __shared__ __align__(16) float Aef[CH * LDA];     // 34.8 KB, persists both cgs
    __shared__ __align__(16) float WbC[64 * LDC];     // 17.4 KB: Wef tile / half C tile
    __shared__ int s_src[CH], s_dst[CH];

    int tid = threadIdx.x;
    int base = blockIdx.x * CH;
    int warp = tid >> 5;
    int wm = warp >> 1, wn = warp & 1;

    // ef tile: fully coalesced stream, async
#pragma unroll
    for (int p = 0; p < 8; p++) {
        int j = tid + 256 * p;
        int row = j >> 4;
        int c4 = j & 15;
        cp16((uint32_t)__cvta_generic_to_shared(Aef + row * LDA + c4 * 4),
             ef + (size_t)(base + row) * EDF + c4 * 4, base + row < E);
    }
    CP_COMMIT();

    if (tid < CH) {
        int e = base + tid;
        bool v = e < E;
        s_src[tid] = v ? ei[e] : 0;
        s_dst[tid] = v ? ei[E + e] : -1;
    }
    CP_WAIT(0);
    __syncthreads();

    int c4 = tid & 15;   // float4 column within the 64-col group
    int rr = tid >> 4;   // 0..15

#pragma unroll 1
    for (int cgi = 0; cgi < 2; cgi++) {
        int cg = blockIdx.y * 2 + cgi;
        // stage Wef[:, cg*64 ..] tile (64 x 64)
#pragma unroll
        for (int p = 0; p < 4; p++) {
            int j = tid + 256 * p;
            int row = j >> 4;
            int cc = j & 15;
            *(float4*)(WbC + row * LDC + cc * 4) =
                *(const float4*)(Wef + (size_t)row * FD + cg * 64 + cc * 4);
        }
        __syncthreads();

        wmma::fragment<wmma::accumulator, 16, 16, 8, float> acc[2][2];
#pragma unroll
        for (int i = 0; i < 2; i++)
#pragma unroll
            for (int j = 0; j < 2; j++) wmma::fill_fragment(acc[i][j], 0.0f);

#pragma unroll
        for (int kk = 0; kk < EDF; kk += 8) {
            wmma::fragment<wmma::matrix_a, 16, 16, 8, wmma::precision::tf32, wmma::row_major> a[2];
            wmma::fragment<wmma::matrix_b, 16, 16, 8, wmma::precision::tf32, wmma::row_major> b[2];
#pragma unroll
            for (int i = 0; i < 2; i++)
                wmma::load_matrix_sync(a[i], Aef + (wm * 32 + i * 16) * LDA + kk, LDA);
#pragma unroll
            for (int j = 0; j < 2; j++)
                wmma::load_matrix_sync(b[j], WbC + kk * LDC + wn * 32 + j * 16, LDC);
#pragma unroll
            for (int i = 0; i < 2; i++)
#pragma unroll
                for (int j = 0; j < 2; j++)
                    wmma::mma_sync(acc[i][j], a[i], b[j], acc[i][j]);
        }
        __syncthreads();  // Wb reads done

        const float4 bv4 = *(const float4*)(bias + cg * 64 + c4 * 4);

        // drain C in two 64-row halves through the 64-row smem buffer
#pragma unroll 1
        for (int hf = 0; hf < 2; hf++) {
            if (wm == hf * 2 || wm == hf * 2 + 1) {
                int lm = wm - hf * 2;  // 0 or 1 -> rows lm*32 .. lm*32+31
#pragma unroll
                for (int i = 0; i < 2; i++)
#pragma unroll
                    for (int j = 0; j < 2; j++)
                        wmma::store_matrix_sync(WbC + (lm * 32 + i * 16) * LDC + wn * 32 + j * 16,
                                                acc[i][j], LDC, wmma::mem_row_major);
            }
            __syncthreads();

            // epilogue: 64 rows, 16 threads per row (one float4 each), 4 passes
#pragma unroll
            for (int it = 0; it < 4; it++) {
                int lrow = it * 16 + rr;         // 0..63 within half
                int row = hf * 64 + lrow;        // 0..127 within tile
                int d = s_dst[row];
                if (d >= 0) {
                    int srow = s_src[row];
                    float4 xs = *(const float4*)(Xs + (size_t)srow * FD + cg * 64 + c4 * 4);
                    float4 xd = *(const float4*)(Xd + (size_t)d * FD + cg * 64 + c4 * 4);
                    float4 cv = *(float4*)(WbC + lrow * LDC + c4 * 4);
                    float4 v;
                    v.x = gelu_f(cv.x + bv4.x + xs.x + xd.x);
                    v.y = gelu_f(cv.y + bv4.y + xs.y + xd.y);
                    v.z = gelu_f(cv.z + bv4.z + xs.z + xd.z);
                    v.w = gelu_f(cv.w + bv4.w + xs.w + xd.w);
                    red_add_v4(out + (size_t)d * FD + cg * 64 + c4 * 4, v);
                }
            }
            __syncthreads();
        }
    }
}

// ---------------- launch ----------------
extern "C" void kernel_launch(void* const* d_in, const int* in_sizes, int n_in,
                              void* d_out, int out_size) {
    const float* x    = (const float*)d_in[0];
    const int* ei     = (const int*)d_in[1];   // int32 (JAX x64 disabled)
    const float* ef   = (const float*)d_in[2];
    const float* Wff1 = (const float*)d_in[3];
    const float* bff1 = (const float*)d_in[4];
    const float* Wmp1 = (const float*)d_in[5];
    const float* bmp1 = (const float*)d_in[6];
    const float* Wmp2 = (const float*)d_in[7];
    const float* bmp2 = (const float*)d_in[8];
    const float* Wff2 = (const float*)d_in[9];
    const float* bff2 = (const float*)d_in[10];

    int N = in_sizes[0] / FD;
    int E = in_sizes[1] / 2;

    float *h0, *h1, *Xs, *Xd, *xr, *efr, *wr;
    cudaGetSymbolAddress((void**)&h0, g_h0);
    cudaGetSymbolAddress((void**)&h1, g_h1);
    cudaGetSymbolAddress((void**)&Xs, g_Xs);
    cudaGetSymbolAddress((void**)&Xd, g_Xd);
    cudaGetSymbolAddress((void**)&xr, g_xr);
    cudaGetSymbolAddress((void**)&efr, g_efr);
    cudaGetSymbolAddress((void**)&wr, g_wr);

    dim3 thr(256);
    int n4 = N * FD / 4;
    long long tot4 = (long long)N * FD / 4 + (long long)E * EDF / 4 + WTOT / 4;

    dim3 gN((N + 127) / 128, 4);
    dim3 gN2((N + 127) / 128, 8);
    dim3 gE((E + 127) / 128, 2);

    // 1: pre-round everything to tf32
    round_all<<<(int)((tot4 + 255) / 256), thr>>>(x, ef, Wff1, Wmp1, Wmp2, Wff2, xr, efr, wr);
    // 2: FFN1 -> h0, dup-write h1 (seed for MP1 aggregation)
    gemm_node<0><<<gN, thr>>>(xr, wr + OW1, nullptr, bff1, nullptr, h0, nullptr, h1, N, 1, 1);
    // 3: dual1 -> Xs, Xd
    gemm_node<0><<<gN2, thr>>>(h0, wr + OM1, wr + OM1 + FD * FD, nullptr, nullptr, Xs, Xd, nullptr, N, 0, 0);
    // 4: edge1 (ncu PROBE) -> h1 += agg
    edge_direct<<<gE, thr>>>(efr, wr + OM1 + 2 * FD * FD, bmp1, Xs, Xd, ei, h1, E);
    // 5: dual2 -> Xs, Xd
    gemm_node<1><<<gN2, thr>>>(h1, wr + OM2, wr + OM2 + FD * FD, nullptr, nullptr, Xs, Xd, nullptr, N, 0, 0);
    // 6: seed h0 = h1
    copy_kernel<<<(n4 + 255) / 256, thr>>>((const float4*)h1, (float4*)h0, n4);
    // 7: edge2 -> h0 += agg
    edge_direct<<<gE, thr>>>(efr, wr + OM2 + 2 * FD * FD, bmp2, Xs, Xd, ei, h0, E);
    // 8: FFN2 + residual -> out
    gemm_node<1><<<gN, thr>>>(h0, wr + OW2, nullptr, bff2, x, (float*)d_out, nullptr, nullptr, N, 0, 0);
}

// round 10
// speedup vs baseline: 1.5258x; 1.5258x over previous
#include <cuda_runtime.h>
#include <mma.h>
#include <cstdint>
#include <cstddef>

using namespace nvcuda;

#define NN 10000
#define NE 320000
#define FD 256
#define EDF 64

// weight offsets inside g_wr
#define OW1 0
#define OM1 (FD * FD)
#define OM2 (OM1 + 576 * FD)
#define OW2 (OM2 + 576 * FD)
#define WTOT (OW2 + FD * FD)

// ---------------- scratch ----------------
__device__ float g_h0[NN * FD];
__device__ float g_h1[NN * FD];
__device__ float g_Xs[NN * FD];
__device__ float g_Xd[NN * FD];
__device__ float g_xr[NN * FD];
__device__ float g_efr[(size_t)NE * EDF];
__device__ float g_wr[WTOT];

__device__ __forceinline__ float gelu_f(float v) {
    float u = 0.7978845608028654f * (v + 0.044715f * v * v * v);
    float t;
    asm("tanh.approx.f32 %0, %1;" : "=f"(t) : "f"(u));
    return 0.5f * v * (1.0f + t);
}

__device__ __forceinline__ void cp16(uint32_t dst, const void* src, bool p) {
    asm volatile("cp.async.ca.shared.global [%0], [%1], 16, %2;"
                 :: "r"(dst), "l"(src), "r"(p ? 16 : 0));
}
#define CP_COMMIT() asm volatile("cp.async.commit_group;")
#define CP_WAIT(n)  asm volatile("cp.async.wait_group %0;" :: "n"(n))

// vectorized fire-and-forget reduction (PTX ISA 8.1, sm_90+)
__device__ __forceinline__ void red_add_v4(float* ptr, float4 v) {
    asm volatile("red.global.add.v4.f32 [%0], {%1, %2, %3, %4};"
                 :: "l"(ptr), "f"(v.x), "f"(v.y), "f"(v.z), "f"(v.w) : "memory");
}

// ---------------- tf32 pre-round: x, ef, all weights in ONE launch ----------------
__global__ void round_all(const float* __restrict__ x, const float* __restrict__ ef,
                          const float* __restrict__ wff1, const float* __restrict__ wmp1,
                          const float* __restrict__ wmp2, const float* __restrict__ wff2,
                          float* __restrict__ xr, float* __restrict__ efr,
                          float* __restrict__ wr) {
    const int NX4 = NN * FD / 4;
    const int NE4 = NE * EDF / 4;
    const int W14 = FD * FD / 4, WM4 = 576 * FD / 4;
    long long i = (long long)blockIdx.x * blockDim.x + threadIdx.x;
    const float4* s;
    float4* d;
    long long j = i;
    if (j < NX4) { s = (const float4*)x; d = (float4*)xr; }
    else {
        j -= NX4;
        if (j < NE4) { s = (const float4*)ef; d = (float4*)efr; }
        else {
            j -= NE4;
            if (j < W14) { s = (const float4*)wff1; d = (float4*)(wr + OW1); }
            else {
                j -= W14;
                if (j < WM4) { s = (const float4*)wmp1; d = (float4*)(wr + OM1); }
                else {
                    j -= WM4;
                    if (j < WM4) { s = (const float4*)wmp2; d = (float4*)(wr + OM2); }
                    else {
                        j -= WM4;
                        if (j >= W14) return;
                        s = (const float4*)wff2; d = (float4*)(wr + OW2);
                    }
                }
            }
        }
    }
    float4 v = s[j];
    v.x = wmma::__float_to_tf32(v.x);
    v.y = wmma::__float_to_tf32(v.y);
    v.z = wmma::__float_to_tf32(v.z);
    v.w = wmma::__float_to_tf32(v.w);
    d[j] = v;
}

__global__ void copy_kernel(const float4* __restrict__ a, float4* __restrict__ b, int n4) {
    int i = blockIdx.x * blockDim.x + threadIdx.x;
    if (i < n4) b[i] = a[i];
}

// ---------------- node GEMM: cp.async 2-stage, cvt-free when inputs pre-rounded ----------------
template <int CVT_A>
__global__ void __launch_bounds__(256) gemm_node(
    const float* __restrict__ A,
    const float* __restrict__ B0, const float* __restrict__ B1,
    const float* __restrict__ bias,
    const float* __restrict__ resid,
    float* __restrict__ C0, float* __restrict__ C1,
    float* __restrict__ Cdup,
    int M, int dogelu, int roundout)
{
    constexpr int BM = 128, BN = 64, BK = 32;
    constexpr int LDA = 36, LDB = 68;
    constexpr int STG = BM * LDA + BK * LDB;
    __shared__ __align__(16) float sm[2 * STG];
    float* Cs = sm;

    int tid = threadIdx.x;
    int warp = tid >> 5;
    int wm = warp >> 1, wn = warp & 1;
    int bm = blockIdx.x * BM;
    int sel = blockIdx.y >> 2;
    int cg = blockIdx.y & 3;
    const float* B = sel ? B1 : B0;
    float* C = sel ? C1 : C0;
    int bn = cg * BN;

    int lra = tid >> 3, lca = (tid & 7) << 2;
    int lrb = tid >> 4, lcb = (tid & 15) << 2;

    auto issue = [&](int st, int k0) {
        float* As = sm + st * STG;
        float* Bs = As + BM * LDA;
#pragma unroll
        for (int p = 0; p < 4; p++) {
            int row = lra + 32 * p;
            int grow = bm + row;
            cp16((uint32_t)__cvta_generic_to_shared(As + row * LDA + lca),
                 A + (size_t)grow * FD + k0 + lca, grow < M);
        }
#pragma unroll
        for (int p = 0; p < 2; p++) {
            int row = lrb + 16 * p;
            cp16((uint32_t)__cvta_generic_to_shared(Bs + row * LDB + lcb),
                 B + (size_t)(k0 + row) * FD + bn + lcb, true);
        }
    };

    wmma::fragment<wmma::accumulator, 16, 16, 8, float> acc[2][2];
#pragma unroll
    for (int i = 0; i < 2; i++)
#pragma unroll
        for (int j = 0; j < 2; j++) wmma::fill_fragment(acc[i][j], 0.0f);

    issue(0, 0);
    CP_COMMIT();

    constexpr int NIT = FD / BK;  // 8
#pragma unroll 1
    for (int it = 0; it < NIT; it++) {
        if (it + 1 < NIT) {
            issue((it + 1) & 1, (it + 1) * BK);
            CP_COMMIT();
            CP_WAIT(1);
        } else {
            CP_WAIT(0);
        }
        __syncthreads();
        float* As = sm + (it & 1) * STG;
        float* Bs = As + BM * LDA;
#pragma unroll
        for (int kk = 0; kk < BK; kk += 8) {
            wmma::fragment<wmma::matrix_a, 16, 16, 8, wmma::precision::tf32, wmma::row_major> a[2];
            wmma::fragment<wmma::matrix_b, 16, 16, 8, wmma::precision::tf32, wmma::row_major> b[2];
#pragma unroll
            for (int i = 0; i < 2; i++) {
                wmma::load_matrix_sync(a[i], As + (wm * 32 + i * 16) * LDA + kk, LDA);
                if (CVT_A) {
#pragma unroll
                    for (int e = 0; e < a[i].num_elements; e++)
                        a[i].x[e] = wmma::__float_to_tf32(a[i].x[e]);
                }
            }
#pragma unroll
            for (int j = 0; j < 2; j++)
                wmma::load_matrix_sync(b[j], Bs + kk * LDB + wn * 32 + j * 16, LDB);
#pragma unroll
            for (int i = 0; i < 2; i++)
#pragma unroll
                for (int j = 0; j < 2; j++)
                    wmma::mma_sync(acc[i][j], a[i], b[j], acc[i][j]);
        }
        __syncthreads();
    }

#pragma unroll
    for (int i = 0; i < 2; i++)
#pragma unroll
        for (int j = 0; j < 2; j++)
            wmma::store_matrix_sync(Cs + (wm * 32 + i * 16) * BN + wn * 32 + j * 16,
                                    acc[i][j], BN, wmma::mem_row_major);
    __syncthreads();
    for (int idx = tid; idx < BM * BN; idx += 256) {
        int r = idx >> 6, c = idx & 63;
        int grow = bm + r;
        if (grow >= M) continue;
        float v = Cs[idx];
        if (bias) v += bias[bn + c];
        if (dogelu) v = gelu_f(v);
        if (roundout) v = wmma::__float_to_tf32(v);
        if (resid) v += resid[(size_t)grow * FD + bn + c];
        C[(size_t)grow * FD + bn + c] = v;
        if (Cdup) Cdup[(size_t)grow * FD + bn + c] = v;
    }
}

// ---------------- direct-order fused edge kernel (R8 structure + v4 reductions) ----------------
// Block: 128 consecutive edges x 2 column groups (grid.y selects which pair).
__global__ void __launch_bounds__(256) edge_direct(
    const float* __restrict__ ef,    // tf32-rounded
    const float* __restrict__ Wef,   // [64, 256] tf32-rounded
    const float* __restrict__ bias,
    const float* __restrict__ Xs, const float* __restrict__ Xd,
    const int* __restrict__ ei,      // src = ei[e], dst = ei[E+e]
    float* __restrict__ out,         // pre-seeded with hin
    int E)
{
    constexpr int CH = 128, LDA = 68, LDB = 68;
    __shared__ __align__(16) float Aef[CH * LDA];    // persists both cgs
    __shared__ __align__(16) float CsWb[CH * LDA];   // Wef tile, then FULL C tile
    __shared__ int s_src[CH], s_dst[CH];

    int tid = threadIdx.x;
    int base = blockIdx.x * CH;
    int warp = tid >> 5;
    int wm = warp >> 1, wn = warp & 1;

    // ef tile: fully coalesced stream, async
#pragma unroll
    for (int p = 0; p < 8; p++) {
        int j = tid + 256 * p;
        int row = j >> 4;
        int c4 = j & 15;
        cp16((uint32_t)__cvta_generic_to_shared(Aef + row * LDA + c4 * 4),
             ef + (size_t)(base + row) * EDF + c4 * 4, base + row < E);
    }
    CP_COMMIT();

    if (tid < CH) {
        int e = base + tid;
        bool v = e < E;
        s_src[tid] = v ? ei[e] : 0;
        s_dst[tid] = v ? ei[E + e] : -1;
    }
    CP_WAIT(0);
    __syncthreads();

    int c4 = tid & 15;   // float4 column within the 64-col group
    int rr = tid >> 4;   // 0..15

#pragma unroll 1
    for (int cgi = 0; cgi < 2; cgi++) {
        int cg = blockIdx.y * 2 + cgi;
        float* Wb = CsWb;
#pragma unroll
        for (int p = 0; p < 4; p++) {
            int j = tid + 256 * p;
            int row = j >> 4;
            int cc = j & 15;
            *(float4*)(Wb + row * LDB + cc * 4) =
                *(const float4*)(Wef + (size_t)row * FD + cg * 64 + cc * 4);
        }
        __syncthreads();

        wmma::fragment<wmma::accumulator, 16, 16, 8, float> acc[2][2];
#pragma unroll
        for (int i = 0; i < 2; i++)
#pragma unroll
            for (int j = 0; j < 2; j++) wmma::fill_fragment(acc[i][j], 0.0f);

#pragma unroll
        for (int kk = 0; kk < EDF; kk += 8) {
            wmma::fragment<wmma::matrix_a, 16, 16, 8, wmma::precision::tf32, wmma::row_major> a[2];
            wmma::fragment<wmma::matrix_b, 16, 16, 8, wmma::precision::tf32, wmma::row_major> b[2];
#pragma unroll
            for (int i = 0; i < 2; i++)
                wmma::load_matrix_sync(a[i], Aef + (wm * 32 + i * 16) * LDA + kk, LDA);
#pragma unroll
            for (int j = 0; j < 2; j++)
                wmma::load_matrix_sync(b[j], Wb + kk * LDB + wn * 32 + j * 16, LDB);
#pragma unroll
            for (int i = 0; i < 2; i++)
#pragma unroll
                for (int j = 0; j < 2; j++)
                    wmma::mma_sync(acc[i][j], a[i], b[j], acc[i][j]);
        }
        __syncthreads();  // Wb reads done

        float* Cs = CsWb;  // full 128-row C tile; accs die right here
#pragma unroll
        for (int i = 0; i < 2; i++)
#pragma unroll
            for (int j = 0; j < 2; j++)
                wmma::store_matrix_sync(Cs + (wm * 32 + i * 16) * LDA + wn * 32 + j * 16,
                                        acc[i][j], LDA, wmma::mem_row_major);
        __syncthreads();

        // epilogue: 16 threads per row, one float4 each; 8 passes; v4 reductions
        const float4 bv4 = *(const float4*)(bias + cg * 64 + c4 * 4);
#pragma unroll
        for (int it = 0; it < 8; it++) {
            int row = it * 16 + rr;
            int d = s_dst[row];
            if (d >= 0) {
                int srow = s_src[row];
                float4 xs = *(const float4*)(Xs + (size_t)srow * FD + cg * 64 + c4 * 4);
                float4 xd = *(const float4*)(Xd + (size_t)d * FD + cg * 64 + c4 * 4);
                float4 cv = *(float4*)(Cs + row * LDA + c4 * 4);
                float4 v;
                v.x = gelu_f(cv.x + bv4.x + xs.x + xd.x);
                v.y = gelu_f(cv.y + bv4.y + xs.y + xd.y);
                v.z = gelu_f(cv.z + bv4.z + xs.z + xd.z);
                v.w = gelu_f(cv.w + bv4.w + xs.w + xd.w);
                red_add_v4(out + (size_t)d * FD + cg * 64 + c4 * 4, v);
            }
        }
        __syncthreads();  // before next cg overwrites CsWb
    }
}

// ---------------- launch ----------------
extern "C" void kernel_launch(void* const* d_in, const int* in_sizes, int n_in,
                              void* d_out, int out_size) {
    const float* x    = (const float*)d_in[0];
    const int* ei     = (const int*)d_in[1];   // int32 (JAX x64 disabled)
    const float* ef   = (const float*)d_in[2];
    const float* Wff1 = (const float*)d_in[3];
    const float* bff1 = (const float*)d_in[4];
    const float* Wmp1 = (const float*)d_in[5];
    const float* bmp1 = (const float*)d_in[6];
    const float* Wmp2 = (const float*)d_in[7];
    const float* bmp2 = (const float*)d_in[8];
    const float* Wff2 = (const float*)d_in[9];
    const float* bff2 = (const float*)d_in[10];

    int N = in_sizes[0] / FD;
    int E = in_sizes[1] / 2;

    float *h0, *h1, *Xs, *Xd, *xr, *efr, *wr;
    cudaGetSymbolAddress((void**)&h0, g_h0);
    cudaGetSymbolAddress((void**)&h1, g_h1);
    cudaGetSymbolAddress((void**)&Xs, g_Xs);
    cudaGetSymbolAddress((void**)&Xd, g_Xd);
    cudaGetSymbolAddress((void**)&xr, g_xr);
    cudaGetSymbolAddress((void**)&efr, g_efr);
    cudaGetSymbolAddress((void**)&wr, g_wr);

    dim3 thr(256);
    int n4 = N * FD / 4;
    long long tot4 = (long long)N * FD / 4 + (long long)E * EDF / 4 + WTOT / 4;

    dim3 gN((N + 127) / 128, 4);
    dim3 gN2((N + 127) / 128, 8);
    dim3 gE((E + 127) / 128, 2);

    // 1: pre-round everything to tf32
    round_all<<<(int)((tot4 + 255) / 256), thr>>>(x, ef, Wff1, Wmp1, Wmp2, Wff2, xr, efr, wr);
    // 2: FFN1 -> h0, dup-write h1 (seed for MP1 aggregation)
    gemm_node<0><<<gN, thr>>>(xr, wr + OW1, nullptr, bff1, nullptr, h0, nullptr, h1, N, 1, 1);
    // 3: dual1 -> Xs, Xd
    gemm_node<0><<<gN2, thr>>>(h0, wr + OM1, wr + OM1 + FD * FD, nullptr, nullptr, Xs, Xd, nullptr, N, 0, 0);
    // 4: edge1 (ncu PROBE) -> h1 += agg
    edge_direct<<<gE, thr>>>(efr, wr + OM1 + 2 * FD * FD, bmp1, Xs, Xd, ei, h1, E);
    // 5: dual2 -> Xs, Xd
    gemm_node<1><<<gN2, thr>>>(h1, wr + OM2, wr + OM2 + FD * FD, nullptr, nullptr, Xs, Xd, nullptr, N, 0, 0);
    // 6: seed h0 = h1
    copy_kernel<<<(n4 + 255) / 256, thr>>>((const float4*)h1, (float4*)h0, n4);
    // 7: edge2 -> h0 += agg
    edge_direct<<<gE, thr>>>(efr, wr + OM2 + 2 * FD * FD, bmp2, Xs, Xd, ei, h0, E);
    // 8: FFN2 + residual -> out
    gemm_node<1><<<gN, thr>>>(h0, wr + OW2, nullptr, bff2, x, (float*)d_out, nullptr, nullptr, N, 0, 0);
}

// round 11
// speedup vs baseline: 1.5748x; 1.0321x over previous
#include <cuda_runtime.h>
#include <mma.h>
#include <cstdint>
#include <cstddef>

using namespace nvcuda;

#define NN 10000
#define NE 320000
#define FD 256
#define EDF 64

// weight offsets inside g_wr
#define OW1 0
#define OM1 (FD * FD)
#define OM2 (OM1 + 576 * FD)
#define OW2 (OM2 + 576 * FD)
#define WTOT (OW2 + FD * FD)

// ---------------- scratch ----------------
__device__ float g_h0[NN * FD];
__device__ float g_Xs[NN * FD];
__device__ float g_Xd[NN * FD];
__device__ float g_xr[NN * FD];
__device__ float g_efr[(size_t)NE * EDF];
__device__ float g_wr[WTOT];

__device__ __forceinline__ float gelu_f(float v) {
    float u = 0.7978845608028654f * (v + 0.044715f * v * v * v);
    float t;
    asm("tanh.approx.f32 %0, %1;" : "=f"(t) : "f"(u));
    return 0.5f * v * (1.0f + t);
}

__device__ __forceinline__ void cp16(uint32_t dst, const void* src, bool p) {
    asm volatile("cp.async.ca.shared.global [%0], [%1], 16, %2;"
                 :: "r"(dst), "l"(src), "r"(p ? 16 : 0));
}
#define CP_COMMIT() asm volatile("cp.async.commit_group;")
#define CP_WAIT(n)  asm volatile("cp.async.wait_group %0;" :: "n"(n))

// vectorized fire-and-forget reduction (PTX ISA 8.1, sm_90+)
__device__ __forceinline__ void red_add_v4(float* ptr, float4 v) {
    asm volatile("red.global.add.v4.f32 [%0], {%1, %2, %3, %4};"
                 :: "l"(ptr), "f"(v.x), "f"(v.y), "f"(v.z), "f"(v.w) : "memory");
}

// ---------------- tf32 pre-round: x, ef, all weights in ONE launch ----------------
__global__ void round_all(const float* __restrict__ x, const float* __restrict__ ef,
                          const float* __restrict__ wff1, const float* __restrict__ wmp1,
                          const float* __restrict__ wmp2, const float* __restrict__ wff2,
                          float* __restrict__ xr, float* __restrict__ efr,
                          float* __restrict__ wr) {
    const int NX4 = NN * FD / 4;
    const int NE4 = NE * EDF / 4;
    const int W14 = FD * FD / 4, WM4 = 576 * FD / 4;
    long long i = (long long)blockIdx.x * blockDim.x + threadIdx.x;
    const float4* s;
    float4* d;
    long long j = i;
    if (j < NX4) { s = (const float4*)x; d = (float4*)xr; }
    else {
        j -= NX4;
        if (j < NE4) { s = (const float4*)ef; d = (float4*)efr; }
        else {
            j -= NE4;
            if (j < W14) { s = (const float4*)wff1; d = (float4*)(wr + OW1); }
            else {
                j -= W14;
                if (j < WM4) { s = (const float4*)wmp1; d = (float4*)(wr + OM1); }
                else {
                    j -= WM4;
                    if (j < WM4) { s = (const float4*)wmp2; d = (float4*)(wr + OM2); }
                    else {
                        j -= WM4;
                        if (j >= W14) return;
                        s = (const float4*)wff2; d = (float4*)(wr + OW2);
                    }
                }
            }
        }
    }
    float4 v = s[j];
    v.x = wmma::__float_to_tf32(v.x);
    v.y = wmma::__float_to_tf32(v.y);
    v.z = wmma::__float_to_tf32(v.z);
    v.w = wmma::__float_to_tf32(v.w);
    d[j] = v;
}

// ---------------- node GEMM: cp.async 2-stage, cvt-free when inputs pre-rounded ----------------
template <int CVT_A>
__global__ void __launch_bounds__(256) gemm_node(
    const float* __restrict__ A,
    const float* __restrict__ B0, const float* __restrict__ B1,
    const float* __restrict__ bias,
    const float* __restrict__ resid,
    float* __restrict__ C0, float* __restrict__ C1,
    int M, int dogelu, int roundout)
{
    constexpr int BM = 128, BN = 64, BK = 32;
    constexpr int LDA = 36, LDB = 68;
    constexpr int STG = BM * LDA + BK * LDB;
    __shared__ __align__(16) float sm[2 * STG];
    float* Cs = sm;

    int tid = threadIdx.x;
    int warp = tid >> 5;
    int wm = warp >> 1, wn = warp & 1;
    int bm = blockIdx.x * BM;
    int sel = blockIdx.y >> 2;
    int cg = blockIdx.y & 3;
    const float* B = sel ? B1 : B0;
    float* C = sel ? C1 : C0;
    int bn = cg * BN;

    int lra = tid >> 3, lca = (tid & 7) << 2;
    int lrb = tid >> 4, lcb = (tid & 15) << 2;

    auto issue = [&](int st, int k0) {
        float* As = sm + st * STG;
        float* Bs = As + BM * LDA;
#pragma unroll
        for (int p = 0; p < 4; p++) {
            int row = lra + 32 * p;
            int grow = bm + row;
            cp16((uint32_t)__cvta_generic_to_shared(As + row * LDA + lca),
                 A + (size_t)grow * FD + k0 + lca, grow < M);
        }
#pragma unroll
        for (int p = 0; p < 2; p++) {
            int row = lrb + 16 * p;
            cp16((uint32_t)__cvta_generic_to_shared(Bs + row * LDB + lcb),
                 B + (size_t)(k0 + row) * FD + bn + lcb, true);
        }
    };

    wmma::fragment<wmma::accumulator, 16, 16, 8, float> acc[2][2];
#pragma unroll
    for (int i = 0; i < 2; i++)
#pragma unroll
        for (int j = 0; j < 2; j++) wmma::fill_fragment(acc[i][j], 0.0f);

    issue(0, 0);
    CP_COMMIT();

    constexpr int NIT = FD / BK;  // 8
#pragma unroll 1
    for (int it = 0; it < NIT; it++) {
        if (it + 1 < NIT) {
            issue((it + 1) & 1, (it + 1) * BK);
            CP_COMMIT();
            CP_WAIT(1);
        } else {
            CP_WAIT(0);
        }
        __syncthreads();
        float* As = sm + (it & 1) * STG;
        float* Bs = As + BM * LDA;
#pragma unroll
        for (int kk = 0; kk < BK; kk += 8) {
            wmma::fragment<wmma::matrix_a, 16, 16, 8, wmma::precision::tf32, wmma::row_major> a[2];
            wmma::fragment<wmma::matrix_b, 16, 16, 8, wmma::precision::tf32, wmma::row_major> b[2];
#pragma unroll
            for (int i = 0; i < 2; i++) {
                wmma::load_matrix_sync(a[i], As + (wm * 32 + i * 16) * LDA + kk, LDA);
                if (CVT_A) {
#pragma unroll
                    for (int e = 0; e < a[i].num_elements; e++)
                        a[i].x[e] = wmma::__float_to_tf32(a[i].x[e]);
                }
            }
#pragma unroll
            for (int j = 0; j < 2; j++)
                wmma::load_matrix_sync(b[j], Bs + kk * LDB + wn * 32 + j * 16, LDB);
#pragma unroll
            for (int i = 0; i < 2; i++)
#pragma unroll
                for (int j = 0; j < 2; j++)
                    wmma::mma_sync(acc[i][j], a[i], b[j], acc[i][j]);
        }
        __syncthreads();
    }

#pragma unroll
    for (int i = 0; i < 2; i++)
#pragma unroll
        for (int j = 0; j < 2; j++)
            wmma::store_matrix_sync(Cs + (wm * 32 + i * 16) * BN + wn * 32 + j * 16,
                                    acc[i][j], BN, wmma::mem_row_major);
    __syncthreads();
    for (int idx = tid; idx < BM * BN; idx += 256) {
        int r = idx >> 6, c = idx & 63;
        int grow = bm + r;
        if (grow >= M) continue;
        float v = Cs[idx];
        if (bias) v += bias[bn + c];
        if (dogelu) v = gelu_f(v);
        if (roundout) v = wmma::__float_to_tf32(v);
        if (resid) v += resid[(size_t)grow * FD + bn + c];
        C[(size_t)grow * FD + bn + c] = v;
    }
}

// ---------------- direct-order fused edge kernel (one cg per block, C reuses Aef) ----------------
// grid = (4, chunks): blockIdx.x = column group (fast dim -> ef tile L2 reuse across cgs),
// blockIdx.y = 128-edge chunk. smem 52 KB -> 4 CTAs/SM.
__global__ void __launch_bounds__(256, 4) edge_direct(
    const float* __restrict__ ef,    // tf32-rounded
    const float* __restrict__ Wef,   // [64, 256] tf32-rounded
    const float* __restrict__ bias,
    const float* __restrict__ Xs, const float* __restrict__ Xd,
    const int* __restrict__ ei,      // src = ei[e], dst = ei[E+e]
    float* __restrict__ out,         // updated in place: out[dst] += gelu(...)
    int E)
{
    constexpr int CH = 128, LDA = 68, LDB = 68;
    __shared__ __align__(16) float Aef[CH * LDA];   // 34816 B; reused as C tile after MMA
    __shared__ __align__(16) float Wb[64 * LDB];    // 17408 B
    __shared__ int s_src[CH], s_dst[CH];

    int tid = threadIdx.x;
    int cg = blockIdx.x;
    int base = blockIdx.y * CH;
    int warp = tid >> 5;
    int wm = warp >> 1, wn = warp & 1;

    // ef tile: fully coalesced stream, async
#pragma unroll
    for (int p = 0; p < 8; p++) {
        int j = tid + 256 * p;
        int row = j >> 4;
        int c4 = j & 15;
        cp16((uint32_t)__cvta_generic_to_shared(Aef + row * LDA + c4 * 4),
             ef + (size_t)(base + row) * EDF + c4 * 4, base + row < E);
    }
    CP_COMMIT();

    if (tid < CH) {
        int e = base + tid;
        bool v = e < E;
        s_src[tid] = v ? ei[e] : 0;
        s_dst[tid] = v ? ei[E + e] : -1;
    }

    // Wef tile (64 x 64), L2-resident
#pragma unroll
    for (int p = 0; p < 4; p++) {
        int j = tid + 256 * p;
        int row = j >> 4;
        int cc = j & 15;
        *(float4*)(Wb + row * LDB + cc * 4) =
            *(const float4*)(Wef + (size_t)row * FD + cg * 64 + cc * 4);
    }
    CP_WAIT(0);
    __syncthreads();

    wmma::fragment<wmma::accumulator, 16, 16, 8, float> acc[2][2];
#pragma unroll
    for (int i = 0; i < 2; i++)
#pragma unroll
        for (int j = 0; j < 2; j++) wmma::fill_fragment(acc[i][j], 0.0f);

#pragma unroll
    for (int kk = 0; kk < EDF; kk += 8) {
        wmma::fragment<wmma::matrix_a, 16, 16, 8, wmma::precision::tf32, wmma::row_major> a[2];
        wmma::fragment<wmma::matrix_b, 16, 16, 8, wmma::precision::tf32, wmma::row_major> b[2];
#pragma unroll
        for (int i = 0; i < 2; i++)
            wmma::load_matrix_sync(a[i], Aef + (wm * 32 + i * 16) * LDA + kk, LDA);
#pragma unroll
        for (int j = 0; j < 2; j++)
            wmma::load_matrix_sync(b[j], Wb + kk * LDB + wn * 32 + j * 16, LDB);
#pragma unroll
        for (int i = 0; i < 2; i++)
#pragma unroll
            for (int j = 0; j < 2; j++)
                wmma::mma_sync(acc[i][j], a[i], b[j], acc[i][j]);
    }
    __syncthreads();  // all Aef reads done -> safe to overwrite with C

    float* Cs = Aef;  // full 128-row C tile; accumulators die here
#pragma unroll
    for (int i = 0; i < 2; i++)
#pragma unroll
        for (int j = 0; j < 2; j++)
            wmma::store_matrix_sync(Cs + (wm * 32 + i * 16) * LDA + wn * 32 + j * 16,
                                    acc[i][j], LDA, wmma::mem_row_major);
    __syncthreads();

    // epilogue: 16 threads per row, one float4 each; 8 passes; v4 reductions
    int c4 = tid & 15;
    int rr = tid >> 4;
    const float4 bv4 = *(const float4*)(bias + cg * 64 + c4 * 4);
#pragma unroll
    for (int it = 0; it < 8; it++) {
        int row = it * 16 + rr;
        int d = s_dst[row];
        if (d >= 0) {
            int srow = s_src[row];
            float4 xs = *(const float4*)(Xs + (size_t)srow * FD + cg * 64 + c4 * 4);
            float4 xd = *(const float4*)(Xd + (size_t)d * FD + cg * 64 + c4 * 4);
            float4 cv = *(float4*)(Cs + row * LDA + c4 * 4);
            float4 v;
            v.x = gelu_f(cv.x + bv4.x + xs.x + xd.x);
            v.y = gelu_f(cv.y + bv4.y + xs.y + xd.y);
            v.z = gelu_f(cv.z + bv4.z + xs.z + xd.z);
            v.w = gelu_f(cv.w + bv4.w + xs.w + xd.w);
            red_add_v4(out + (size_t)d * FD + cg * 64 + c4 * 4, v);
        }
    }
}

// ---------------- launch ----------------
extern "C" void kernel_launch(void* const* d_in, const int* in_sizes, int n_in,
                              void* d_out, int out_size) {
    const float* x    = (const float*)d_in[0];
    const int* ei     = (const int*)d_in[1];   // int32 (JAX x64 disabled)
    const float* ef   = (const float*)d_in[2];
    const float* Wff1 = (const float*)d_in[3];
    const float* bff1 = (const float*)d_in[4];
    const float* Wmp1 = (const float*)d_in[5];
    const float* bmp1 = (const float*)d_in[6];
    const float* Wmp2 = (const float*)d_in[7];
    const float* bmp2 = (const float*)d_in[8];
    const float* Wff2 = (const float*)d_in[9];
    const float* bff2 = (const float*)d_in[10];

    int N = in_sizes[0] / FD;
    int E = in_sizes[1] / 2;

    float *h0, *Xs, *Xd, *xr, *efr, *wr;
    cudaGetSymbolAddress((void**)&h0, g_h0);
    cudaGetSymbolAddress((void**)&Xs, g_Xs);
    cudaGetSymbolAddress((void**)&Xd, g_Xd);
    cudaGetSymbolAddress((void**)&xr, g_xr);
    cudaGetSymbolAddress((void**)&efr, g_efr);
    cudaGetSymbolAddress((void**)&wr, g_wr);

    dim3 thr(256);
    long long tot4 = (long long)N * FD / 4 + (long long)E * EDF / 4 + WTOT / 4;

    dim3 gN((N + 127) / 128, 4);
    dim3 gN2((N + 127) / 128, 8);
    dim3 gE(4, (E + 127) / 128);   // cg fast dim -> ef tile L2 reuse across cgs

    // 1: pre-round everything to tf32
    round_all<<<(int)((tot4 + 255) / 256), thr>>>(x, ef, Wff1, Wmp1, Wmp2, Wff2, xr, efr, wr);
    // 2: FFN1 -> h0 (tf32-rounded output)
    gemm_node<0><<<gN, thr>>>(xr, wr + OW1, nullptr, bff1, nullptr, h0, nullptr, N, 1, 1);
    // 3: dual1 -> Xs, Xd
    gemm_node<0><<<gN2, thr>>>(h0, wr + OM1, wr + OM1 + FD * FD, nullptr, nullptr, Xs, Xd, N, 0, 0);
    // 4: edge1 (ncu PROBE): h0 += agg1 (in place; reads only Xs/Xd/ef)
    edge_direct<<<gE, thr>>>(efr, wr + OM1 + 2 * FD * FD, bmp1, Xs, Xd, ei, h0, E);
    // 5: dual2 -> Xs, Xd (h0 now raw fp32 -> cvt A in-kernel)
    gemm_node<1><<<gN2, thr>>>(h0, wr + OM2, wr + OM2 + FD * FD, nullptr, nullptr, Xs, Xd, N, 0, 0);
    // 6: edge2: h0 += agg2 (in place)
    edge_direct<<<gE, thr>>>(efr, wr + OM2 + 2 * FD * FD, bmp2, Xs, Xd, ei, h0, E);
    // 7: FFN2 + residual -> out
    gemm_node<1><<<gN, thr>>>(h0, wr + OW2, nullptr, bff2, x, (float*)d_out, nullptr, N, 0, 0);
}

// round 12
// speedup vs baseline: 2.1709x; 1.3785x over previous
#include <cuda_runtime.h>
#include <cuda_fp16.h>
#include <mma.h>
#include <cstdint>
#include <cstddef>

using namespace nvcuda;

#define NN 10000
#define NE 320000
#define FD 256
#define EDF 64

// weight offsets inside g_wh (halves)
#define OW1 0
#define OM1 (FD * FD)
#define OM2 (OM1 + 576 * FD)
#define OW2 (OM2 + 576 * FD)
#define WTOT (OW2 + FD * FD)

// ---------------- scratch ----------------
__device__ float  g_h0[NN * FD];
__device__ __half g_h0h[NN * FD];
__device__ __half g_Xsh[NN * FD];
__device__ __half g_Xdh[NN * FD];
__device__ __half g_xh[NN * FD];
__device__ __half g_efh[(size_t)NE * EDF];
__device__ __half g_wh[WTOT];

__device__ __forceinline__ float gelu_f(float v) {
    float u = 0.7978845608028654f * (v + 0.044715f * v * v * v);
    float t;
    asm("tanh.approx.f32 %0, %1;" : "=f"(t) : "f"(u));
    return 0.5f * v * (1.0f + t);
}

__device__ __forceinline__ void cp16(uint32_t dst, const void* src, bool p) {
    asm volatile("cp.async.ca.shared.global [%0], [%1], 16, %2;"
                 :: "r"(dst), "l"(src), "r"(p ? 16 : 0));
}
#define CP_COMMIT() asm volatile("cp.async.commit_group;")
#define CP_WAIT(n)  asm volatile("cp.async.wait_group %0;" :: "n"(n))

// vectorized fire-and-forget reduction (PTX ISA 8.1, sm_90+)
__device__ __forceinline__ void red_add_v4(float* ptr, float4 v) {
    asm volatile("red.global.add.v4.f32 [%0], {%1, %2, %3, %4};"
                 :: "l"(ptr), "f"(v.x), "f"(v.y), "f"(v.z), "f"(v.w) : "memory");
}

// ---------------- fp32 -> fp16 conversion: x, ef, all weights in ONE launch ----------------
__global__ void convert_all(const float* __restrict__ x, const float* __restrict__ ef,
                            const float* __restrict__ wff1, const float* __restrict__ wmp1,
                            const float* __restrict__ wmp2, const float* __restrict__ wff2,
                            __half* __restrict__ xh, __half* __restrict__ efh,
                            __half* __restrict__ wh) {
    const int NX4 = NN * FD / 4;
    const int NE4 = NE * EDF / 4;
    const int W14 = FD * FD / 4, WM4 = 576 * FD / 4;
    long long i = (long long)blockIdx.x * blockDim.x + threadIdx.x;
    const float4* s;
    __half* d;
    long long j = i;
    if (j < NX4) { s = (const float4*)x; d = xh; }
    else {
        j -= NX4;
        if (j < NE4) { s = (const float4*)ef; d = efh; }
        else {
            j -= NE4;
            if (j < W14) { s = (const float4*)wff1; d = wh + OW1; }
            else {
                j -= W14;
                if (j < WM4) { s = (const float4*)wmp1; d = wh + OM1; }
                else {
                    j -= WM4;
                    if (j < WM4) { s = (const float4*)wmp2; d = wh + OM2; }
                    else {
                        j -= WM4;
                        if (j >= W14) return;
                        s = (const float4*)wff2; d = wh + OW2;
                    }
                }
            }
        }
    }
    float4 v = s[j];
    __half2* dd = (__half2*)(d + j * 4);
    dd[0] = __floats2half2_rn(v.x, v.y);
    dd[1] = __floats2half2_rn(v.z, v.w);
}

// h0 (fp32, post-atomics) -> h0h (half)
__global__ void cvt_h0(const float4* __restrict__ a, __half2* __restrict__ b, int n4) {
    int i = blockIdx.x * blockDim.x + threadIdx.x;
    if (i < n4) {
        float4 v = a[i];
        b[i * 2]     = __floats2half2_rn(v.x, v.y);
        b[i * 2 + 1] = __floats2half2_rn(v.z, v.w);
    }
}

// ---------------- node GEMM: fp16 in, fp32 acc, cp.async 2-stage ----------------
// C = op(A[M,256] @ B[256,256] + bias [+resid]); grid.y: sel=y>>2, cg=y&3.
__global__ void __launch_bounds__(256) gemm_node(
    const __half* __restrict__ A,
    const __half* __restrict__ B0, const __half* __restrict__ B1,
    const float* __restrict__ bias,
    const float* __restrict__ resid,
    float* __restrict__ C0f, float* __restrict__ C1f,
    __half* __restrict__ C0h, __half* __restrict__ C1h,
    int M, int dogelu)
{
    constexpr int BM = 128, BN = 64, BK = 32;
    constexpr int LDA = 40, LDB = 72;                 // halves
    constexpr int STG = BM * LDA + BK * LDB;          // 7424 halves per stage
    __shared__ __align__(16) char smraw[BM * BN * 4]; // 32 KB; stages then C tile
    __half* sm = (__half*)smraw;
    float* Cs = (float*)smraw;

    int tid = threadIdx.x;
    int warp = tid >> 5;
    int wm = warp >> 1, wn = warp & 1;
    int bm = blockIdx.x * BM;
    int sel = blockIdx.y >> 2;
    int cg = blockIdx.y & 3;
    const __half* B = sel ? B1 : B0;
    float* Cf = sel ? C1f : C0f;
    __half* Ch = sel ? C1h : C0h;
    int bn = cg * BN;

    auto issue = [&](int st, int k0) {
        __half* As = sm + st * STG;
        __half* Bs = As + BM * LDA;
        // A tile: 128 rows x 32 halves = 4 chunks/row -> 512 chunks, 2 passes
#pragma unroll
        for (int p = 0; p < 2; p++) {
            int j = tid + 256 * p;
            int row = j >> 2, ch = j & 3;
            int grow = bm + row;
            cp16((uint32_t)__cvta_generic_to_shared(As + row * LDA + ch * 8),
                 A + (size_t)grow * FD + k0 + ch * 8, grow < M);
        }
        // B tile: 32 rows x 64 halves = 8 chunks/row -> 256 chunks, 1 pass
        {
            int row = tid >> 3, ch = tid & 7;
            cp16((uint32_t)__cvta_generic_to_shared(Bs + row * LDB + ch * 8),
                 B + (size_t)(k0 + row) * FD + bn + ch * 8, true);
        }
    };

    wmma::fragment<wmma::accumulator, 16, 16, 16, float> acc[2][2];
#pragma unroll
    for (int i = 0; i < 2; i++)
#pragma unroll
        for (int j = 0; j < 2; j++) wmma::fill_fragment(acc[i][j], 0.0f);

    issue(0, 0);
    CP_COMMIT();

    constexpr int NIT = FD / BK;  // 8
#pragma unroll 1
    for (int it = 0; it < NIT; it++) {
        if (it + 1 < NIT) {
            issue((it + 1) & 1, (it + 1) * BK);
            CP_COMMIT();
            CP_WAIT(1);
        } else {
            CP_WAIT(0);
        }
        __syncthreads();
        __half* As = sm + (it & 1) * STG;
        __half* Bs = As + BM * LDA;
#pragma unroll
        for (int kk = 0; kk < BK; kk += 16) {
            wmma::fragment<wmma::matrix_a, 16, 16, 16, __half, wmma::row_major> a[2];
            wmma::fragment<wmma::matrix_b, 16, 16, 16, __half, wmma::row_major> b[2];
#pragma unroll
            for (int i = 0; i < 2; i++)
                wmma::load_matrix_sync(a[i], As + (wm * 32 + i * 16) * LDA + kk, LDA);
#pragma unroll
            for (int j = 0; j < 2; j++)
                wmma::load_matrix_sync(b[j], Bs + kk * LDB + wn * 32 + j * 16, LDB);
#pragma unroll
            for (int i = 0; i < 2; i++)
#pragma unroll
                for (int j = 0; j < 2; j++)
                    wmma::mma_sync(acc[i][j], a[i], b[j], acc[i][j]);
        }
        __syncthreads();
    }

#pragma unroll
    for (int i = 0; i < 2; i++)
#pragma unroll
        for (int j = 0; j < 2; j++)
            wmma::store_matrix_sync(Cs + (wm * 32 + i * 16) * BN + wn * 32 + j * 16,
                                    acc[i][j], BN, wmma::mem_row_major);
    __syncthreads();
    for (int idx = tid; idx < BM * BN; idx += 256) {
        int r = idx >> 6, c = idx & 63;
        int grow = bm + r;
        if (grow >= M) continue;
        float v = Cs[idx];
        if (bias) v += bias[bn + c];
        if (dogelu) v = gelu_f(v);
        if (resid) v += resid[(size_t)grow * FD + bn + c];
        if (Cf) Cf[(size_t)grow * FD + bn + c] = v;
        if (Ch) Ch[(size_t)grow * FD + bn + c] = __float2half(v);
    }
}

// ---------------- direct-order fused edge kernel (fp16 MMA, fp32 acc + atomics) ----------------
// grid = (4, chunks): blockIdx.x = column group (fast dim -> ef tile L2 reuse),
// blockIdx.y = 128-edge chunk. smem ~36 KB; regs capped for 5 CTAs/SM.
__global__ void __launch_bounds__(256, 5) edge_direct(
    const __half* __restrict__ ef,   // half
    const __half* __restrict__ Wef,  // [64, 256] half
    const float* __restrict__ bias,
    const __half* __restrict__ Xs, const __half* __restrict__ Xd,
    const int* __restrict__ ei,      // src = ei[e], dst = ei[E+e]
    float* __restrict__ out,         // updated in place: out[dst] += gelu(...)
    int E)
{
    constexpr int CH = 128, LDA = 72, LDB = 72, LDC = 68;
    // union: [Aef 128x72 half | Wb 64x72 half] (27648 B) then C tile 128x68 fp32 (34816 B)
    __shared__ __align__(16) char smraw[CH * LDC * 4];
    __half* Aef = (__half*)smraw;
    __half* Wb  = Aef + CH * LDA;
    float*  Cs  = (float*)smraw;
    __shared__ int s_src[CH], s_dst[CH];

    int tid = threadIdx.x;
    int cg = blockIdx.x;
    int base = blockIdx.y * CH;
    int warp = tid >> 5;
    int wm = warp >> 1, wn = warp & 1;

    // ef tile: 128 rows x 64 halves = 8 chunks/row -> 1024 chunks, 4 passes (async)
#pragma unroll
    for (int p = 0; p < 4; p++) {
        int j = tid + 256 * p;
        int row = j >> 3, ch = j & 7;
        cp16((uint32_t)__cvta_generic_to_shared(Aef + row * LDA + ch * 8),
             ef + (size_t)(base + row) * EDF + ch * 8, base + row < E);
    }
    // Wef tile: 64 rows x 64 halves -> 512 chunks, 2 passes (async)
#pragma unroll
    for (int p = 0; p < 2; p++) {
        int j = tid + 256 * p;
        int row = j >> 3, ch = j & 7;
        cp16((uint32_t)__cvta_generic_to_shared(Wb + row * LDB + ch * 8),
             Wef + (size_t)row * FD + cg * 64 + ch * 8, true);
    }
    CP_COMMIT();

    if (tid < CH) {
        int e = base + tid;
        bool v = e < E;
        s_src[tid] = v ? ei[e] : 0;
        s_dst[tid] = v ? ei[E + e] : -1;
    }
    CP_WAIT(0);
    __syncthreads();

    wmma::fragment<wmma::accumulator, 16, 16, 16, float> acc[2][2];
#pragma unroll
    for (int i = 0; i < 2; i++)
#pragma unroll
        for (int j = 0; j < 2; j++) wmma::fill_fragment(acc[i][j], 0.0f);

#pragma unroll
    for (int kk = 0; kk < EDF; kk += 16) {
        wmma::fragment<wmma::matrix_a, 16, 16, 16, __half, wmma::row_major> a[2];
        wmma::fragment<wmma::matrix_b, 16, 16, 16, __half, wmma::row_major> b[2];
#pragma unroll
        for (int i = 0; i < 2; i++)
            wmma::load_matrix_sync(a[i], Aef + (wm * 32 + i * 16) * LDA + kk, LDA);
#pragma unroll
        for (int j = 0; j < 2; j++)
            wmma::load_matrix_sync(b[j], Wb + kk * LDB + wn * 32 + j * 16, LDB);
#pragma unroll
        for (int i = 0; i < 2; i++)
#pragma unroll
            for (int j = 0; j < 2; j++)
                wmma::mma_sync(acc[i][j], a[i], b[j], acc[i][j]);
    }
    __syncthreads();  // Aef + Wb reads done -> safe to overwrite with fp32 C

#pragma unroll
    for (int i = 0; i < 2; i++)
#pragma unroll
        for (int j = 0; j < 2; j++)
            wmma::store_matrix_sync(Cs + (wm * 32 + i * 16) * LDC + wn * 32 + j * 16,
                                    acc[i][j], LDC, wmma::mem_row_major);
    __syncthreads();

    // epilogue: 16 threads per row, one float4-of-columns each; 8 passes; v4 reds
    int c4 = tid & 15;
    int rr = tid >> 4;
    const float4 bv4 = *(const float4*)(bias + cg * 64 + c4 * 4);
#pragma unroll
    for (int it = 0; it < 8; it++) {
        int row = it * 16 + rr;
        int d = s_dst[row];
        if (d >= 0) {
            int srow = s_src[row];
            const __half2* xsp = (const __half2*)(Xs + (size_t)srow * FD + cg * 64 + c4 * 4);
            const __half2* xdp = (const __half2*)(Xd + (size_t)d * FD + cg * 64 + c4 * 4);
            float2 xs01 = __half22float2(xsp[0]);
            float2 xs23 = __half22float2(xsp[1]);
            float2 xd01 = __half22float2(xdp[0]);
            float2 xd23 = __half22float2(xdp[1]);
            float4 cv = *(float4*)(Cs + row * LDC + c4 * 4);
            float4 v;
            v.x = gelu_f(cv.x + bv4.x + xs01.x + xd01.x);
            v.y = gelu_f(cv.y + bv4.y + xs01.y + xd01.y);
            v.z = gelu_f(cv.z + bv4.z + xs23.x + xd23.x);
            v.w = gelu_f(cv.w + bv4.w + xs23.y + xd23.y);
            red_add_v4(out + (size_t)d * FD + cg * 64 + c4 * 4, v);
        }
    }
}

// ---------------- launch ----------------
extern "C" void kernel_launch(void* const* d_in, const int* in_sizes, int n_in,
                              void* d_out, int out_size) {
    const float* x    = (const float*)d_in[0];
    const int* ei     = (const int*)d_in[1];   // int32 (JAX x64 disabled)
    const float* ef   = (const float*)d_in[2];
    const float* Wff1 = (const float*)d_in[3];
    const float* bff1 = (const float*)d_in[4];
    const float* Wmp1 = (const float*)d_in[5];
    const float* bmp1 = (const float*)d_in[6];
    const float* Wmp2 = (const float*)d_in[7];
    const float* bmp2 = (const float*)d_in[8];
    const float* Wff2 = (const float*)d_in[9];
    const float* bff2 = (const float*)d_in[10];

    int N = in_sizes[0] / FD;
    int E = in_sizes[1] / 2;

    float* h0;
    __half *h0h, *Xsh, *Xdh, *xh, *efh, *wh;
    cudaGetSymbolAddress((void**)&h0, g_h0);
    cudaGetSymbolAddress((void**)&h0h, g_h0h);
    cudaGetSymbolAddress((void**)&Xsh, g_Xsh);
    cudaGetSymbolAddress((void**)&Xdh, g_Xdh);
    cudaGetSymbolAddress((void**)&xh, g_xh);
    cudaGetSymbolAddress((void**)&efh, g_efh);
    cudaGetSymbolAddress((void**)&wh, g_wh);

    dim3 thr(256);
    int n4 = N * FD / 4;
    long long tot4 = (long long)N * FD / 4 + (long long)E * EDF / 4 + WTOT / 4;

    dim3 gN((N + 127) / 128, 4);
    dim3 gN2((N + 127) / 128, 8);
    dim3 gE(4, (E + 127) / 128);   // cg fast dim -> ef tile L2 reuse across cgs

    // 1: convert inputs/weights to fp16
    convert_all<<<(int)((tot4 + 255) / 256), thr>>>(x, ef, Wff1, Wmp1, Wmp2, Wff2, xh, efh, wh);
    // 2: FFN1 -> h0 (fp32) + h0h (half)
    gemm_node<<<gN, thr>>>(xh, wh + OW1, nullptr, bff1, nullptr, h0, nullptr, h0h, nullptr, N, 1);
    // 3: dual1 -> Xsh, Xdh (half)
    gemm_node<<<gN2, thr>>>(h0h, wh + OM1, wh + OM1 + FD * FD, nullptr, nullptr,
                            nullptr, nullptr, Xsh, Xdh, N, 0);
    // 4: edge1 (ncu PROBE): h0 += agg1 (fp32 atomics, in place)
    edge_direct<<<gE, thr>>>(efh, wh + OM1 + 2 * FD * FD, bmp1, Xsh, Xdh, ei, h0, E);
    // 5: h0 -> h0h
    cvt_h0<<<(n4 + 255) / 256, thr>>>((const float4*)h0, (__half2*)h0h, n4);
    // 6: dual2 -> Xsh, Xdh
    gemm_node<<<gN2, thr>>>(h0h, wh + OM2, wh + OM2 + FD * FD, nullptr, nullptr,
                            nullptr, nullptr, Xsh, Xdh, N, 0);
    // 7: edge2: h0 += agg2 (in place)
    edge_direct<<<gE, thr>>>(efh, wh + OM2 + 2 * FD * FD, bmp2, Xsh, Xdh, ei, h0, E);
    // 8: h0 -> h0h
    cvt_h0<<<(n4 + 255) / 256, thr>>>((const float4*)h0, (__half2*)h0h, n4);
    // 9: FFN2 + residual -> out
    gemm_node<<<gN, thr>>>(h0h, wh + OW2, nullptr, bff2, x, (float*)d_out, nullptr,
                           nullptr, nullptr, N, 0);
}

// round 13
// speedup vs baseline: 2.9433x; 1.3558x over previous
#include <cuda_runtime.h>
#include <cuda_fp16.h>
#include <mma.h>
#include <cstdint>
#include <cstddef>

using namespace nvcuda;

#define NN 10000
#define NE 320000
#define FD 256
#define EDF 64

// weight offsets inside g_wh (halves)
#define OW1 0
#define OM1 (FD * FD)
#define OM2 (OM1 + 576 * FD)
#define OW2 (OM2 + 576 * FD)
#define WTOT (OW2 + FD * FD)

// ---------------- scratch ----------------
__device__ float  g_h0[NN * FD];
__device__ __half g_h0h[NN * FD];
__device__ __half g_Xsh[NN * FD];
__device__ __half g_Xdh[NN * FD];
__device__ __half g_xh[NN * FD];
__device__ __half g_efh[(size_t)NE * EDF];
__device__ __half g_wh[WTOT];
__device__ int g_rowptr[NN + 1];
__device__ int g_cnt[NN];
__device__ int g_ofs[NN];
__device__ int g_srcs[NE];
__device__ int g_dsts[NE];
__device__ int g_eids[NE];

__device__ __forceinline__ float gelu_f(float v) {
    float u = 0.7978845608028654f * (v + 0.044715f * v * v * v);
    float t;
    asm("tanh.approx.f32 %0, %1;" : "=f"(t) : "f"(u));
    return 0.5f * v * (1.0f + t);
}

__device__ __forceinline__ void cp16(uint32_t dst, const void* src, bool p) {
    asm volatile("cp.async.ca.shared.global [%0], [%1], 16, %2;"
                 :: "r"(dst), "l"(src), "r"(p ? 16 : 0));
}
#define CP_COMMIT() asm volatile("cp.async.commit_group;")
#define CP_WAIT(n)  asm volatile("cp.async.wait_group %0;" :: "n"(n))

__device__ __forceinline__ void red_add_v4(float* ptr, float4 v) {
    asm volatile("red.global.add.v4.f32 [%0], {%1, %2, %3, %4};"
                 :: "l"(ptr), "f"(v.x), "f"(v.y), "f"(v.z), "f"(v.w) : "memory");
}

// ---------------- fp32 -> fp16 conversion: x, ef, all weights in ONE launch ----------------
__global__ void convert_all(const float* __restrict__ x, const float* __restrict__ ef,
                            const float* __restrict__ wff1, const float* __restrict__ wmp1,
                            const float* __restrict__ wmp2, const float* __restrict__ wff2,
                            __half* __restrict__ xh, __half* __restrict__ efh,
                            __half* __restrict__ wh) {
    const int NX4 = NN * FD / 4;
    const int NE4 = NE * EDF / 4;
    const int W14 = FD * FD / 4, WM4 = 576 * FD / 4;
    long long i = (long long)blockIdx.x * blockDim.x + threadIdx.x;
    const float4* s;
    __half* d;
    long long j = i;
    if (j < NX4) { s = (const float4*)x; d = xh; }
    else {
        j -= NX4;
        if (j < NE4) { s = (const float4*)ef; d = efh; }
        else {
            j -= NE4;
            if (j < W14) { s = (const float4*)wff1; d = wh + OW1; }
            else {
                j -= W14;
                if (j < WM4) { s = (const float4*)wmp1; d = wh + OM1; }
                else {
                    j -= WM4;
                    if (j < WM4) { s = (const float4*)wmp2; d = wh + OM2; }
                    else {
                        j -= WM4;
                        if (j >= W14) return;
                        s = (const float4*)wff2; d = wh + OW2;
                    }
                }
            }
        }
    }
    float4 v = s[j];
    __half2* dd = (__half2*)(d + j * 4);
    dd[0] = __floats2half2_rn(v.x, v.y);
    dd[1] = __floats2half2_rn(v.z, v.w);
}

// h0 (fp32, post-atomics) -> h0h (half)
__global__ void cvt_h0(const float4* __restrict__ a, __half2* __restrict__ b, int n4) {
    int i = blockIdx.x * blockDim.x + threadIdx.x;
    if (i < n4) {
        float4 v = a[i];
        b[i * 2]     = __floats2half2_rn(v.x, v.y);
        b[i * 2 + 1] = __floats2half2_rn(v.z, v.w);
    }
}

// ---------------- CSR construction (sort edges by dst; built once, used twice) ----------------
__global__ void zero_kernel(int* __restrict__ p, int n) {
    int i = blockIdx.x * blockDim.x + threadIdx.x;
    if (i < n) p[i] = 0;
}

__global__ void hist_kernel(const int* __restrict__ ei, int* __restrict__ cnt, int E) {
    int e = blockIdx.x * blockDim.x + threadIdx.x;
    if (e < E) atomicAdd(&cnt[ei[E + e]], 1);
}

__global__ void scan_kernel(const int* __restrict__ cnt, int* __restrict__ rowptr,
                            int* __restrict__ ofs, int n) {
    __shared__ int part[1024];
    const int PER = 16;
    int t = threadIdx.x;
    int base = t * PER;
    int local[PER];
    int s = 0;
#pragma unroll
    for (int j = 0; j < PER; j++) {
        int idx = base + j;
        int c = (idx < n) ? cnt[idx] : 0;
        local[j] = s;
        s += c;
    }
    part[t] = s;
    __syncthreads();
    for (int off = 1; off < 1024; off <<= 1) {
        int v = (t >= off) ? part[t - off] : 0;
        __syncthreads();
        part[t] += v;
        __syncthreads();
    }
    int pre = (t > 0) ? part[t - 1] : 0;
#pragma unroll
    for (int j = 0; j < PER; j++) {
        int idx = base + j;
        if (idx < n) {
            int v = pre + local[j];
            rowptr[idx] = v;
            ofs[idx] = v;
        }
    }
    if (t == 1023) rowptr[n] = part[1023];
}

__global__ void scatter_kernel(const int* __restrict__ ei, int* __restrict__ ofs,
                               int* __restrict__ srcs, int* __restrict__ dsts,
                               int* __restrict__ eids, int E) {
    int e = blockIdx.x * blockDim.x + threadIdx.x;
    if (e < E) {
        int d = ei[E + e];
        int p = atomicAdd(&ofs[d], 1);
        srcs[p] = ei[e];
        dsts[p] = d;
        eids[p] = e;
    }
}

// ---------------- node GEMM: fp16 in, fp32 acc, cp.async 2-stage ----------------
__global__ void __launch_bounds__(256) gemm_node(
    const __half* __restrict__ A,
    const __half* __restrict__ B0, const __half* __restrict__ B1,
    const float* __restrict__ bias,
    const float* __restrict__ resid,
    float* __restrict__ C0f, float* __restrict__ C1f,
    __half* __restrict__ C0h, __half* __restrict__ C1h,
    int M, int dogelu)
{
    constexpr int BM = 128, BN = 64, BK = 32;
    constexpr int LDA = 40, LDB = 72;
    constexpr int STG = BM * LDA + BK * LDB;
    __shared__ __align__(16) char smraw[BM * BN * 4];
    __half* sm = (__half*)smraw;
    float* Cs = (float*)smraw;

    int tid = threadIdx.x;
    int warp = tid >> 5;
    int wm = warp >> 1, wn = warp & 1;
    int bm = blockIdx.x * BM;
    int sel = blockIdx.y >> 2;
    int cg = blockIdx.y & 3;
    const __half* B = sel ? B1 : B0;
    float* Cf = sel ? C1f : C0f;
    __half* Ch = sel ? C1h : C0h;
    int bn = cg * BN;

    auto issue = [&](int st, int k0) {
        __half* As = sm + st * STG;
        __half* Bs = As + BM * LDA;
#pragma unroll
        for (int p = 0; p < 2; p++) {
            int j = tid + 256 * p;
            int row = j >> 2, ch = j & 3;
            int grow = bm + row;
            cp16((uint32_t)__cvta_generic_to_shared(As + row * LDA + ch * 8),
                 A + (size_t)grow * FD + k0 + ch * 8, grow < M);
        }
        {
            int row = tid >> 3, ch = tid & 7;
            cp16((uint32_t)__cvta_generic_to_shared(Bs + row * LDB + ch * 8),
                 B + (size_t)(k0 + row) * FD + bn + ch * 8, true);
        }
    };

    wmma::fragment<wmma::accumulator, 16, 16, 16, float> acc[2][2];
#pragma unroll
    for (int i = 0; i < 2; i++)
#pragma unroll
        for (int j = 0; j < 2; j++) wmma::fill_fragment(acc[i][j], 0.0f);

    issue(0, 0);
    CP_COMMIT();

    constexpr int NIT = FD / BK;  // 8
#pragma unroll 1
    for (int it = 0; it < NIT; it++) {
        if (it + 1 < NIT) {
            issue((it + 1) & 1, (it + 1) * BK);
            CP_COMMIT();
            CP_WAIT(1);
        } else {
            CP_WAIT(0);
        }
        __syncthreads();
        __half* As = sm + (it & 1) * STG;
        __half* Bs = As + BM * LDA;
#pragma unroll
        for (int kk = 0; kk < BK; kk += 16) {
            wmma::fragment<wmma::matrix_a, 16, 16, 16, __half, wmma::row_major> a[2];
            wmma::fragment<wmma::matrix_b, 16, 16, 16, __half, wmma::row_major> b[2];
#pragma unroll
            for (int i = 0; i < 2; i++)
                wmma::load_matrix_sync(a[i], As + (wm * 32 + i * 16) * LDA + kk, LDA);
#pragma unroll
            for (int j = 0; j < 2; j++)
                wmma::load_matrix_sync(b[j], Bs + kk * LDB + wn * 32 + j * 16, LDB);
#pragma unroll
            for (int i = 0; i < 2; i++)
#pragma unroll
                for (int j = 0; j < 2; j++)
                    wmma::mma_sync(acc[i][j], a[i], b[j], acc[i][j]);
        }
        __syncthreads();
    }

#pragma unroll
    for (int i = 0; i < 2; i++)
#pragma unroll
        for (int j = 0; j < 2; j++)
            wmma::store_matrix_sync(Cs + (wm * 32 + i * 16) * BN + wn * 32 + j * 16,
                                    acc[i][j], BN, wmma::mem_row_major);
    __syncthreads();
    for (int idx = tid; idx < BM * BN; idx += 256) {
        int r = idx >> 6, c = idx & 63;
        int grow = bm + r;
        if (grow >= M) continue;
        float v = Cs[idx];
        if (bias) v += bias[bn + c];
        if (dogelu) v = gelu_f(v);
        if (resid) v += resid[(size_t)grow * FD + bn + c];
        if (Cf) Cf[(size_t)grow * FD + bn + c] = v;
        if (Ch) Ch[(size_t)grow * FD + bn + c] = __float2half(v);
    }
}

// ---------------- dst-sorted fused edge kernel (fp16 MMA, segment-reduced epilogue) ----------------
// grid = (4, chunks): blockIdx.x = column group, blockIdx.y = 128-edge chunk (dst-sorted order).
__global__ void __launch_bounds__(256, 4) edge_sorted(
    const __half* __restrict__ ef,   // half
    const __half* __restrict__ Wef,  // [64, 256] half
    const float* __restrict__ bias,
    const __half* __restrict__ Xs, const __half* __restrict__ Xd,
    float* __restrict__ out,         // updated in place: out[dst] += gelu(...)
    int E)
{
    constexpr int CH = 128, LDA = 72, LDB = 72, LDC = 68;
    __shared__ __align__(16) char smraw[CH * LDC * 4];
    __half* Aef = (__half*)smraw;
    __half* Wb  = Aef + CH * LDA;
    float*  Cs  = (float*)smraw;
    __shared__ int s_src[CH], s_dst[CH], s_eid[CH];

    int tid = threadIdx.x;
    int cg = blockIdx.x;
    int base = blockIdx.y * CH;
    int warp = tid >> 5;
    int wm = warp >> 1, wn = warp & 1;

    if (tid < CH) {
        int i = base + tid;
        bool v = i < E;
        s_eid[tid] = v ? g_eids[i] : -1;
        s_src[tid] = v ? g_srcs[i] : 0;
        s_dst[tid] = v ? g_dsts[i] : -1;
    }
    __syncthreads();

    // gather ef rows (128B each, 8 chunks/row) by sorted eid
#pragma unroll
    for (int p = 0; p < 4; p++) {
        int j = tid + 256 * p;
        int row = j >> 3, ch = j & 7;
        int e = s_eid[row];
        cp16((uint32_t)__cvta_generic_to_shared(Aef + row * LDA + ch * 8),
             ef + (size_t)(e < 0 ? 0 : e) * EDF + ch * 8, e >= 0);
    }
    // Wef tile (64x64, L2-resident)
#pragma unroll
    for (int p = 0; p < 2; p++) {
        int j = tid + 256 * p;
        int row = j >> 3, ch = j & 7;
        cp16((uint32_t)__cvta_generic_to_shared(Wb + row * LDB + ch * 8),
             Wef + (size_t)row * FD + cg * 64 + ch * 8, true);
    }
    CP_COMMIT();
    CP_WAIT(0);
    __syncthreads();

    wmma::fragment<wmma::accumulator, 16, 16, 16, float> acc[2][2];
#pragma unroll
    for (int i = 0; i < 2; i++)
#pragma unroll
        for (int j = 0; j < 2; j++) wmma::fill_fragment(acc[i][j], 0.0f);

#pragma unroll
    for (int kk = 0; kk < EDF; kk += 16) {
        wmma::fragment<wmma::matrix_a, 16, 16, 16, __half, wmma::row_major> a[2];
        wmma::fragment<wmma::matrix_b, 16, 16, 16, __half, wmma::row_major> b[2];
#pragma unroll
        for (int i = 0; i < 2; i++)
            wmma::load_matrix_sync(a[i], Aef + (wm * 32 + i * 16) * LDA + kk, LDA);
#pragma unroll
        for (int j = 0; j < 2; j++)
            wmma::load_matrix_sync(b[j], Wb + kk * LDB + wn * 32 + j * 16, LDB);
#pragma unroll
        for (int i = 0; i < 2; i++)
#pragma unroll
            for (int j = 0; j < 2; j++)
                wmma::mma_sync(acc[i][j], a[i], b[j], acc[i][j]);
    }
    __syncthreads();  // Aef + Wb reads done -> safe to overwrite with fp32 C

#pragma unroll
    for (int i = 0; i < 2; i++)
#pragma unroll
        for (int j = 0; j < 2; j++)
            wmma::store_matrix_sync(Cs + (wm * 32 + i * 16) * LDC + wn * 32 + j * 16,
                                    acc[i][j], LDC, wmma::mem_row_major);
    __syncthreads();

    // epilogue: 16 threads per row-group, thread owns 4 cols x 8 CONSECUTIVE rows;
    // dsts are sorted -> accumulate per segment, one Xd load + one red.v4 per segment.
    int c4 = tid & 15;
    int rr = tid >> 4;           // 0..15 -> rows rr*8 .. rr*8+7
    const float4 bv4 = *(const float4*)(bias + cg * 64 + c4 * 4);
    float4 accv = make_float4(0.f, 0.f, 0.f, 0.f);
    float4 xd4 = make_float4(0.f, 0.f, 0.f, 0.f);
    int prev = -1;
#pragma unroll
    for (int it = 0; it < 8; it++) {
        int row = rr * 8 + it;
        int d = s_dst[row];
        if (d < 0) break;
        if (d != prev) {
            if (prev >= 0)
                red_add_v4(out + (size_t)prev * FD + cg * 64 + c4 * 4, accv);
            prev = d;
            accv = make_float4(0.f, 0.f, 0.f, 0.f);
            const __half2* xdp = (const __half2*)(Xd + (size_t)d * FD + cg * 64 + c4 * 4);
            float2 a01 = __half22float2(xdp[0]);
            float2 a23 = __half22float2(xdp[1]);
            xd4 = make_float4(a01.x, a01.y, a23.x, a23.y);
        }
        const __half2* xsp = (const __half2*)(Xs + (size_t)s_src[row] * FD + cg * 64 + c4 * 4);
        float2 s01 = __half22float2(xsp[0]);
        float2 s23 = __half22float2(xsp[1]);
        float4 cv = *(float4*)(Cs + row * LDC + c4 * 4);
        accv.x += gelu_f(cv.x + bv4.x + s01.x + xd4.x);
        accv.y += gelu_f(cv.y + bv4.y + s01.y + xd4.y);
        accv.z += gelu_f(cv.z + bv4.z + s23.x + xd4.z);
        accv.w += gelu_f(cv.w + bv4.w + s23.y + xd4.w);
    }
    if (prev >= 0)
        red_add_v4(out + (size_t)prev * FD + cg * 64 + c4 * 4, accv);
}

// ---------------- launch ----------------
extern "C" void kernel_launch(void* const* d_in, const int* in_sizes, int n_in,
                              void* d_out, int out_size) {
    const float* x    = (const float*)d_in[0];
    const int* ei     = (const int*)d_in[1];   // int32 (JAX x64 disabled)
    const float* ef   = (const float*)d_in[2];
    const float* Wff1 = (const float*)d_in[3];
    const float* bff1 = (const float*)d_in[4];
    const float* Wmp1 = (const float*)d_in[5];
    const float* bmp1 = (const float*)d_in[6];
    const float* Wmp2 = (const float*)d_in[7];
    const float* bmp2 = (const float*)d_in[8];
    const float* Wff2 = (const float*)d_in[9];
    const float* bff2 = (const float*)d_in[10];

    int N = in_sizes[0] / FD;
    int E = in_sizes[1] / 2;

    float* h0;
    __half *h0h, *Xsh, *Xdh, *xh, *efh, *wh;
    int *rowptr, *cnt, *ofs, *srcs, *dsts, *eids;
    cudaGetSymbolAddress((void**)&h0, g_h0);
    cudaGetSymbolAddress((void**)&h0h, g_h0h);
    cudaGetSymbolAddress((void**)&Xsh, g_Xsh);
    cudaGetSymbolAddress((void**)&Xdh, g_Xdh);
    cudaGetSymbolAddress((void**)&xh, g_xh);
    cudaGetSymbolAddress((void**)&efh, g_efh);
    cudaGetSymbolAddress((void**)&wh, g_wh);
    cudaGetSymbolAddress((void**)&rowptr, g_rowptr);
    cudaGetSymbolAddress((void**)&cnt, g_cnt);
    cudaGetSymbolAddress((void**)&ofs, g_ofs);
    cudaGetSymbolAddress((void**)&srcs, g_srcs);
    cudaGetSymbolAddress((void**)&dsts, g_dsts);
    cudaGetSymbolAddress((void**)&eids, g_eids);

    dim3 thr(256);
    int eb = (E + 255) / 256;
    int n4 = N * FD / 4;
    long long tot4 = (long long)N * FD / 4 + (long long)E * EDF / 4 + WTOT / 4;

    dim3 gN((N + 127) / 128, 4);
    dim3 gN2((N + 127) / 128, 8);
    dim3 gE(4, (E + 127) / 128);

    // 1: convert inputs/weights to fp16
    convert_all<<<(int)((tot4 + 255) / 256), thr>>>(x, ef, Wff1, Wmp1, Wmp2, Wff2, xh, efh, wh);
    // 2-3: CSR prefix
    zero_kernel<<<(N + 255) / 256, thr>>>(cnt, N);
    hist_kernel<<<eb, thr>>>(ei, cnt, E);
    // 4: FFN1 (ncu PROBE: first look at the fp16 GEMM)
    gemm_node<<<gN, thr>>>(xh, wh + OW1, nullptr, bff1, nullptr, h0, nullptr, h0h, nullptr, N, 1);
    // 5-6: finish CSR (sorted by dst; reused by both edge layers)
    scan_kernel<<<1, 1024>>>(cnt, rowptr, ofs, N);
    scatter_kernel<<<eb, thr>>>(ei, ofs, srcs, dsts, eids, E);
    // 7: dual1 -> Xsh, Xdh
    gemm_node<<<gN2, thr>>>(h0h, wh + OM1, wh + OM1 + FD * FD, nullptr, nullptr,
                            nullptr, nullptr, Xsh, Xdh, N, 0);
    // 8: edge1: h0 += agg1 (fp32 atomics, in place)
    edge_sorted<<<gE, thr>>>(efh, wh + OM1 + 2 * FD * FD, bmp1, Xsh, Xdh, h0, E);
    // 9: h0 -> h0h
    cvt_h0<<<(n4 + 255) / 256, thr>>>((const float4*)h0, (__half2*)h0h, n4);
    // 10: dual2 -> Xsh, Xdh
    gemm_node<<<gN2, thr>>>(h0h, wh + OM2, wh + OM2 + FD * FD, nullptr, nullptr,
                            nullptr, nullptr, Xsh, Xdh, N, 0);
    // 11: edge2: h0 += agg2 (in place)
    edge_sorted<<<gE, thr>>>(efh, wh + OM2 + 2 * FD * FD, bmp2, Xsh, Xdh, h0, E);
    // 12: h0 -> h0h
    cvt_h0<<<(n4 + 255) / 256, thr>>>((const float4*)h0, (__half2*)h0h, n4);
    // 13: FFN2 + residual -> out
    gemm_node<<<gN, thr>>>(h0h, wh + OW2, nullptr, bff2, x, (float*)d_out, nullptr,
                           nullptr, nullptr, N, 0);
}